// round 16
// baseline (speedup 1.0000x reference)
#include <cuda_runtime.h>
#include <cuda_fp16.h>
#include <mma.h>
#include <cstdint>
#include <math.h>

using namespace nvcuda;

#define NNODES 4096
#define TN2    8192
#define DIM    128
#define FDIM   256
#define NEDGE  65536

// ================= scratch (device globals; no allocation) =================
__device__ float g_X[TN2 * DIM];
__device__ float g_Vb[TN2 * DIM];
__device__ float g_F[TN2 * FDIM];
__device__ float g_L[TN2];            // exp row sums
__device__ float g_OP[2 * TN2 * DIM]; // PV partials (2 key-halves)
__device__ __half g_Xh[TN2 * DIM];    // fp16(X) for QKV linears
__device__ __half g_Qh[TN2 * DIM];    // fp16(Q * isc)
__device__ __half g_Kh[TN2 * DIM];    // fp16(K)
__device__ __half g_Vth[DIM * TN2];   // fp16(V^T)
__device__ __half g_Fh[TN2 * DIM];    // fp16(final feats) for adj
__device__ __half g_MEANh[TN2 * FDIM];
__device__ __half g_F256h[TN2 * FDIM];
// CSR for combined graph (both graphs, nodes 0..8191)
__device__ int g_cnt[TN2];
__device__ int g_off[TN2];
__device__ int g_cur[TN2];
__device__ int g_elist[2 * NEDGE];

// ================= small elementwise kernels =================
__global__ void concat_x(const float* __restrict__ x1, const float* __restrict__ x2,
                         float* __restrict__ X, __half* __restrict__ Xh) {
    int i = blockIdx.x * blockDim.x + threadIdx.x;
    if (i < TN2 * DIM) {
        float v = (i < NNODES * DIM) ? x1[i] : x2[i - NNODES * DIM];
        X[i] = v;
        Xh[i] = __float2half(v);
    }
}
__global__ void zero_f(float* __restrict__ p, int n) {
    int i = blockIdx.x * blockDim.x + threadIdx.x;
    if (i < n) p[i] = 0.f;
}
__global__ void zero_i(int* __restrict__ p, int n) {
    int i = blockIdx.x * blockDim.x + threadIdx.x;
    if (i < n) p[i] = 0;
}
// ---- CSR build (once; graph static across layers) ----
__global__ void edge_count(const int* __restrict__ ei, int off, int* __restrict__ cnt) {
    int e = blockIdx.x * blockDim.x + threadIdx.x;
    if (e < NEDGE) atomicAdd(&cnt[ei[NEDGE + e] + off], 1);
}
__global__ void scan_offsets(const int* __restrict__ cnt, int* __restrict__ off) {
    __shared__ int tsum[1024];
    int t = threadIdx.x;
    int local[8];
    int s = 0;
#pragma unroll
    for (int j = 0; j < 8; j++) { local[j] = s; s += cnt[t * 8 + j]; }
    tsum[t] = s;
    __syncthreads();
    for (int d = 1; d < 1024; d <<= 1) {
        int v = (t >= d) ? tsum[t - d] : 0;
        __syncthreads();
        tsum[t] += v;
        __syncthreads();
    }
    int base = (t == 0) ? 0 : tsum[t - 1];
#pragma unroll
    for (int j = 0; j < 8; j++) off[t * 8 + j] = base + local[j];
}
__global__ void fill_edges(const int* __restrict__ ei, int noff,
                           const int* __restrict__ off, int* __restrict__ cur,
                           int* __restrict__ elist) {
    int e = blockIdx.x * blockDim.x + threadIdx.x;
    if (e < NEDGE) {
        int src = ei[e] + noff;
        int dst = ei[NEDGE + e] + noff;
        int p = atomicAdd(&cur[dst], 1);
        elist[off[dst] + p] = src;
    }
}
// ---- gather-mean -> fp16 ----
__global__ void gather_mean(const float* __restrict__ F, const int* __restrict__ off,
                            const int* __restrict__ cnt, const int* __restrict__ elist,
                            __half* __restrict__ meanh) {
    int row = blockIdx.x;
    int c = threadIdx.x;
    int base = off[row], n = cnt[row];
    float s = 0.f;
    for (int i = 0; i < n; i++) {
        int src = elist[base + i];
        s += F[(size_t)src * FDIM + c];
    }
    meanh[(size_t)row * FDIM + c] = __float2half(s / (float)max(n, 1));
}
// F = [X, X - O], fp32 for gather + fp16 for sage lin_r
__global__ void build_feats2(const float* __restrict__ X, const float* __restrict__ OP,
                             const float* __restrict__ l, float* __restrict__ F,
                             __half* __restrict__ F256h) {
    int i = blockIdx.x * blockDim.x + threadIdx.x;
    if (i < TN2 * DIM) {
        int row = i >> 7, c = i & 127;
        float x = X[i];
        float o = (OP[i] + OP[TN2 * DIM + i]) / l[row];
        float d = x - o;
        F[row * FDIM + c] = x;
        F[row * FDIM + DIM + c] = d;
        F256h[(size_t)row * FDIM + c] = __float2half(x);
        F256h[(size_t)row * FDIM + DIM + c] = __float2half(d);
    }
}
__global__ void round_f16(const float* __restrict__ in, __half* __restrict__ out) {
    int i = blockIdx.x * blockDim.x + threadIdx.x;
    if (i < TN2 * DIM) out[i] = __float2half(in[i]);
}
// V [8192,128] fp32 -> Vt [128,8192] fp16 (64-key tiles)
__global__ void vt_round_f16(const float* __restrict__ V, __half* __restrict__ Vth) {
    __shared__ float t[64][132];
    int tid = threadIdx.x;
    int k0 = blockIdx.x * 64;
#pragma unroll
    for (int rep = 0; rep < 8; rep++) {
        int idx = rep * 256 + tid;
        int r = idx >> 5, c4 = (idx & 31) * 4;
        float4 v = *(const float4*)&V[(k0 + r) * DIM + c4];
        t[r][c4] = v.x; t[r][c4 + 1] = v.y; t[r][c4 + 2] = v.z; t[r][c4 + 3] = v.w;
    }
    __syncthreads();
    int d = tid >> 1, half_ = tid & 1;
    size_t base = (size_t)d * TN2 + k0 + half_ * 32;
#pragma unroll
    for (int j = 0; j < 32; j++)
        Vth[base + j] = __float2half(t[half_ * 32 + j][d]);
}

// ======== WMMA linear: C[128,128]/block = Ah[128,128] @ fp16(W*scale) + bias*scale ====
// mode 0: write fp16 to outH; mode 1: write fp32 to outF.
#define LSTR 136
#define LTILE (128 * LSTR)                       // halves per A/B tile
#define QKV_SMEM (2 * LTILE * 2 + 16 * 132 * 4)  // 69632 + 8448 = 78080 B

__global__ __launch_bounds__(256) void qkv_wmma(
    const __half* __restrict__ Ah, const float* __restrict__ W,
    const float* __restrict__ bias, float scale, int mode,
    __half* __restrict__ outH, float* __restrict__ outF) {
    extern __shared__ char sm[];
    __half* sA = (__half*)sm;
    __half* sB = sA + LTILE;
    float* sBias = (float*)(sm + 2 * LTILE * 2);
    int tid = threadIdx.x, lane = tid & 31, w = tid >> 5;
    int m0 = blockIdx.x * 128;

#pragma unroll
    for (int rep = 0; rep < 8; rep++) {          // FIXED: 128 rows (was rep<4 = 64 rows)
        int u = rep * 256 + tid;
        int row = u >> 4, c8 = (u & 15) * 8;
        *(uint4*)&sA[row * LSTR + c8] = *(const uint4*)&Ah[(size_t)(m0 + row) * DIM + c8];
    }
#pragma unroll
    for (int rep = 0; rep < 16; rep++) {
        int u = rep * 256 + tid;
        int row = u >> 5, c4 = (u & 31) * 4;
        float4 v = *(const float4*)&W[row * DIM + c4];
        sB[row * LSTR + c4 + 0] = __float2half(v.x * scale);
        sB[row * LSTR + c4 + 1] = __float2half(v.y * scale);
        sB[row * LSTR + c4 + 2] = __float2half(v.z * scale);
        sB[row * LSTR + c4 + 3] = __float2half(v.w * scale);
    }
#pragma unroll
    for (int rep = 0; rep < 8; rep++) {
        int u = rep * 256 + tid;
        int row = u >> 7, c = u & 127;
        sBias[row * 132 + c] = bias[c] * scale;
    }
    __syncthreads();

    wmma::fragment<wmma::accumulator, 16, 16, 16, float> acc[8];
#pragma unroll
    for (int n = 0; n < 8; n++)
        wmma::load_matrix_sync(acc[n], sBias + n * 16, 132, wmma::mem_row_major);
#pragma unroll
    for (int ks = 0; ks < 8; ks++) {
        wmma::fragment<wmma::matrix_a, 16, 16, 16, __half, wmma::row_major> a;
        wmma::load_matrix_sync(a, sA + (w * 16) * LSTR + ks * 16, LSTR);
#pragma unroll
        for (int n = 0; n < 8; n++) {
            wmma::fragment<wmma::matrix_b, 16, 16, 16, __half, wmma::row_major> b;
            wmma::load_matrix_sync(b, sB + (ks * 16) * LSTR + n * 16, LSTR);
            wmma::mma_sync(acc[n], a, b, acc[n]);
        }
    }
    __syncthreads();

    float* mC = (float*)sm + w * (16 * 132);
#pragma unroll
    for (int n = 0; n < 8; n++)
        wmma::store_matrix_sync(mC + n * 16, acc[n], 132, wmma::mem_row_major);
    __syncwarp();
    int r = lane >> 1, c0 = (lane & 1) * 64;
    size_t gbase = (size_t)(m0 + w * 16 + r) * DIM + c0;
    if (mode == 0) {
#pragma unroll
        for (int j = 0; j < 64; j++) outH[gbase + j] = __float2half(mC[r * 132 + c0 + j]);
    } else {
#pragma unroll
        for (int j = 0; j < 64; j++) outF[gbase + j] = mC[r * 132 + c0 + j];
    }
}

// ======== WMMA fused SAGE: X = MEANh@Wl + bl + F256h@Wr (+relu); writes fp32+fp16 ====
__global__ __launch_bounds__(256) void sage_wmma(
    const __half* __restrict__ Mh, const __half* __restrict__ Fh256,
    const float* __restrict__ Wl, const float* __restrict__ Wr,
    const float* __restrict__ bl, int relu,
    float* __restrict__ Xout, __half* __restrict__ XhOut) {
    extern __shared__ char sm[];
    __half* sA = (__half*)sm;
    __half* sB = sA + LTILE;
    float* sBias = (float*)(sm + 2 * LTILE * 2);
    int tid = threadIdx.x, lane = tid & 31, w = tid >> 5;
    int m0 = blockIdx.x * 128;

#pragma unroll
    for (int rep = 0; rep < 8; rep++) {
        int u = rep * 256 + tid;
        int row = u >> 7, c = u & 127;
        sBias[row * 132 + c] = bl[c];
    }
    __syncthreads();
    wmma::fragment<wmma::accumulator, 16, 16, 16, float> acc[8];
#pragma unroll
    for (int n = 0; n < 8; n++)
        wmma::load_matrix_sync(acc[n], sBias + n * 16, 132, wmma::mem_row_major);

#pragma unroll
    for (int p = 0; p < 2; p++) {
        const __half* Ap = p ? Fh256 : Mh;
        const float* Wp = p ? Wr : Wl;
#pragma unroll
        for (int kc = 0; kc < 2; kc++) {
            __syncthreads();
#pragma unroll
            for (int rep = 0; rep < 8; rep++) {  // FIXED: 128 rows (was rep<4 = 64 rows)
                int u = rep * 256 + tid;
                int row = u >> 4, c8 = (u & 15) * 8;
                *(uint4*)&sA[row * LSTR + c8] =
                    *(const uint4*)&Ap[(size_t)(m0 + row) * FDIM + kc * 128 + c8];
            }
#pragma unroll
            for (int rep = 0; rep < 16; rep++) {
                int u = rep * 256 + tid;
                int row = u >> 5, c4 = (u & 31) * 4;
                float4 v = *(const float4*)&Wp[(kc * 128 + row) * DIM + c4];
                sB[row * LSTR + c4 + 0] = __float2half(v.x);
                sB[row * LSTR + c4 + 1] = __float2half(v.y);
                sB[row * LSTR + c4 + 2] = __float2half(v.z);
                sB[row * LSTR + c4 + 3] = __float2half(v.w);
            }
            __syncthreads();
#pragma unroll
            for (int ks = 0; ks < 8; ks++) {
                wmma::fragment<wmma::matrix_a, 16, 16, 16, __half, wmma::row_major> a;
                wmma::load_matrix_sync(a, sA + (w * 16) * LSTR + ks * 16, LSTR);
#pragma unroll
                for (int n = 0; n < 8; n++) {
                    wmma::fragment<wmma::matrix_b, 16, 16, 16, __half, wmma::row_major> b;
                    wmma::load_matrix_sync(b, sB + (ks * 16) * LSTR + n * 16, LSTR);
                    wmma::mma_sync(acc[n], a, b, acc[n]);
                }
            }
        }
    }
    __syncthreads();

    float* mC = (float*)sm + w * (16 * 132);
#pragma unroll
    for (int n = 0; n < 8; n++)
        wmma::store_matrix_sync(mC + n * 16, acc[n], 132, wmma::mem_row_major);
    __syncwarp();
    int r = lane >> 1, c0 = (lane & 1) * 64;
    size_t gbase = (size_t)(m0 + w * 16 + r) * DIM + c0;
#pragma unroll
    for (int j = 0; j < 64; j++) {
        float v = mC[r * 132 + c0 + j];
        if (relu) v = fmaxf(v, 0.f);
        Xout[gbase + j] = v;
        XhOut[gbase + j] = __float2half(v);
    }
}

// ======== fused flash attention: pure fp16 single-term (R13-proven version) ========
#define QSTR 136
#define VSTR 72
#define OFF_Q  0
#define OFF_K  (OFF_Q + 128 * QSTR)
#define OFF_V  (OFF_K + 64 * QSTR)
#define HB     ((OFF_V + 128 * VSTR) * 2)    // 70656 B
#define SB     (8 * 16 * 68 * 4)             // 34816 B
#define PB     (8 * 16 * 72 * 2)             // 18432 B
#define FL_SMEM (HB + SB + PB)               // 123904 B

__global__ __launch_bounds__(256, 1) void flash_f16(
    const __half* __restrict__ Qh, const __half* __restrict__ Kh,
    const __half* __restrict__ Vth, float* __restrict__ OP,
    float* __restrict__ lsum) {
    extern __shared__ char smc[];
    __half* sb = (__half*)smc;
    float* sS = (float*)(smc + HB);
    __half* sP = (__half*)(smc + HB + SB);

    int tid = threadIdx.x, lane = tid & 31, w = tid >> 5;
    int m0 = blockIdx.x * 128;
    int kh = blockIdx.y;
    int kbase = kh * (TN2 / 2);

#pragma unroll
    for (int rep = 0; rep < 8; rep++) {
        int u = rep * 256 + tid;
        int row = u >> 4, c8 = (u & 15) * 8;
        *(uint4*)&sb[OFF_Q + row * QSTR + c8] =
            *(const uint4*)&Qh[(size_t)(m0 + row) * DIM + c8];
    }

    wmma::fragment<wmma::accumulator, 16, 16, 16, float> oacc[8];
#pragma unroll
    for (int n = 0; n < 8; n++) wmma::fill_fragment(oacc[n], 0.f);
    float rs = 0.f;
    float* mS = sS + w * (16 * 68);
    __half* mP = sP + w * (16 * 72);

    for (int c = 0; c < 64; c++) {
        int kc = kbase + c * 64;
        __syncthreads();
#pragma unroll
        for (int rep = 0; rep < 4; rep++) {
            int u = rep * 256 + tid;
            int row = u >> 4, c8 = (u & 15) * 8;
            *(uint4*)&sb[OFF_K + row * QSTR + c8] =
                *(const uint4*)&Kh[(size_t)(kc + row) * DIM + c8];
        }
#pragma unroll
        for (int rep = 0; rep < 4; rep++) {
            int u = rep * 256 + tid;
            int row = u >> 3, c8 = (u & 7) * 8;
            *(uint4*)&sb[OFF_V + row * VSTR + c8] =
                *(const uint4*)&Vth[(size_t)row * TN2 + kc + c8];
        }
        __syncthreads();

        wmma::fragment<wmma::accumulator, 16, 16, 16, float> sf[4];
#pragma unroll
        for (int n = 0; n < 4; n++) wmma::fill_fragment(sf[n], 0.f);
#pragma unroll
        for (int ks = 0; ks < 8; ks++) {
            wmma::fragment<wmma::matrix_a, 16, 16, 16, __half, wmma::row_major> a;
            wmma::load_matrix_sync(a, sb + OFF_Q + (w * 16) * QSTR + ks * 16, QSTR);
#pragma unroll
            for (int n = 0; n < 4; n++) {
                wmma::fragment<wmma::matrix_b, 16, 16, 16, __half, wmma::col_major> b;
                wmma::load_matrix_sync(b, sb + OFF_K + (n * 16) * QSTR + ks * 16, QSTR);
                wmma::mma_sync(sf[n], a, b, sf[n]);
            }
        }
#pragma unroll
        for (int n = 0; n < 4; n++)
            wmma::store_matrix_sync(mS + n * 16, sf[n], 68, wmma::mem_row_major);
        __syncwarp();

        {
            int r = lane >> 1, c0 = (lane & 1) * 32;
            float rsl = 0.f;
#pragma unroll
            for (int j = 0; j < 32; j++) {
                float e = __expf(mS[r * 68 + c0 + j]);
                rsl += e;
                mP[r * 72 + c0 + j] = __float2half(e);
            }
            rs += rsl;
        }
        __syncwarp();

#pragma unroll
        for (int kt = 0; kt < 4; kt++) {
            wmma::fragment<wmma::matrix_a, 16, 16, 16, __half, wmma::row_major> pa;
            wmma::load_matrix_sync(pa, mP + kt * 16, 72);
#pragma unroll
            for (int n = 0; n < 8; n++) {
                wmma::fragment<wmma::matrix_b, 16, 16, 16, __half, wmma::col_major> v;
                wmma::load_matrix_sync(v, sb + OFF_V + (n * 16) * VSTR + kt * 16, VSTR);
                wmma::mma_sync(oacc[n], pa, v, oacc[n]);
            }
        }
    }

    float* dst = OP + (size_t)kh * TN2 * DIM + (size_t)(m0 + w * 16) * DIM;
#pragma unroll
    for (int n = 0; n < 8; n++)
        wmma::store_matrix_sync(dst + n * 16, oacc[n], DIM, wmma::mem_row_major);
    rs += __shfl_xor_sync(0xffffffffu, rs, 1);
    if ((lane & 1) == 0) atomicAdd(&lsum[m0 + w * 16 + (lane >> 1)], rs);
}

// ======== fp16 NT GEMM + sigmoid: out = sigmoid(F F^T), K=128 staged whole ====
#define ASTR 136
#define ADJ_TILE (128 * ASTR)
#define ADJ_SMEM (2 * ADJ_TILE * 2)   // 69632 B -> 3 CTAs/SM

__global__ __launch_bounds__(256, 3) void adj_sigmoid(
    const __half* __restrict__ Fh, float* __restrict__ outF) {
    extern __shared__ __half smb[];
    int tid = threadIdx.x, w = tid >> 5;
    int wm = (w & 3) * 32, wn = (w >> 2) * 64;
    int m0 = blockIdx.x * 128, n0 = blockIdx.y * 128;
    __half* sA = smb;
    __half* sB = smb + ADJ_TILE;

#pragma unroll
    for (int rep = 0; rep < 8; rep++) {
        int u = rep * 256 + tid;
        int row = u >> 4, c8 = (u & 15) * 8;
        *(uint4*)&sA[row * ASTR + c8] = *(const uint4*)&Fh[(size_t)(m0 + row) * DIM + c8];
        *(uint4*)&sB[row * ASTR + c8] = *(const uint4*)&Fh[(size_t)(n0 + row) * DIM + c8];
    }
    __syncthreads();

    wmma::fragment<wmma::accumulator, 16, 16, 16, float> acc[2][4];
#pragma unroll
    for (int mt = 0; mt < 2; mt++)
#pragma unroll
        for (int nt = 0; nt < 4; nt++) wmma::fill_fragment(acc[mt][nt], 0.f);

#pragma unroll
    for (int ks = 0; ks < 8; ks++) {
        wmma::fragment<wmma::matrix_a, 16, 16, 16, __half, wmma::row_major> a[2];
#pragma unroll
        for (int mt = 0; mt < 2; mt++)
            wmma::load_matrix_sync(a[mt], sA + (wm + mt * 16) * ASTR + ks * 16, ASTR);
#pragma unroll
        for (int nt = 0; nt < 4; nt++) {
            wmma::fragment<wmma::matrix_b, 16, 16, 16, __half, wmma::col_major> b;
            wmma::load_matrix_sync(b, sB + (wn + nt * 16) * ASTR + ks * 16, ASTR);
#pragma unroll
            for (int mt = 0; mt < 2; mt++)
                wmma::mma_sync(acc[mt][nt], a[mt], b, acc[mt][nt]);
        }
    }

#pragma unroll
    for (int mt = 0; mt < 2; mt++)
#pragma unroll
        for (int nt = 0; nt < 4; nt++) {
#pragma unroll
            for (int i = 0; i < acc[mt][nt].num_elements; i++)
                acc[mt][nt].x[i] = 1.f / (1.f + __expf(-acc[mt][nt].x[i]));
            float* dst = outF + (size_t)(m0 + wm + mt * 16) * TN2 + n0 + wn + nt * 16;
            wmma::store_matrix_sync(dst, acc[mt][nt], TN2, wmma::mem_row_major);
        }
}

// ================= host orchestration =================
extern "C" void kernel_launch(void* const* d_in, const int* in_sizes, int n_in,
                              void* d_out, int out_size) {
    const float* x1 = (const float*)d_in[0];
    const float* x2 = (const float*)d_in[1];
    const int* ei1 = (const int*)d_in[2];
    const int* ei2 = (const int*)d_in[3];
    const float* Wk[2] = {(const float*)d_in[4], (const float*)d_in[13]};
    const float* bk[2] = {(const float*)d_in[5], (const float*)d_in[14]};
    const float* Wq[2] = {(const float*)d_in[6], (const float*)d_in[15]};
    const float* bq[2] = {(const float*)d_in[7], (const float*)d_in[16]};
    const float* Wv[2] = {(const float*)d_in[8], (const float*)d_in[17]};
    const float* bv[2] = {(const float*)d_in[9], (const float*)d_in[18]};
    const float* Wl[2] = {(const float*)d_in[10], (const float*)d_in[19]};
    const float* bl[2] = {(const float*)d_in[11], (const float*)d_in[20]};
    const float* Wr[2] = {(const float*)d_in[12], (const float*)d_in[21]};
    float* out = (float*)d_out;

    float *pX, *pV, *pF, *pL, *pOP;
    __half *pXh, *pQh, *pKh, *pVth, *pFh, *pMh, *pF256h;
    int *pCnt, *pOff, *pCur, *pEl;
    cudaGetSymbolAddress((void**)&pX, g_X);
    cudaGetSymbolAddress((void**)&pV, g_Vb);
    cudaGetSymbolAddress((void**)&pF, g_F);
    cudaGetSymbolAddress((void**)&pL, g_L);
    cudaGetSymbolAddress((void**)&pOP, g_OP);
    cudaGetSymbolAddress((void**)&pXh, g_Xh);
    cudaGetSymbolAddress((void**)&pQh, g_Qh);
    cudaGetSymbolAddress((void**)&pKh, g_Kh);
    cudaGetSymbolAddress((void**)&pVth, g_Vth);
    cudaGetSymbolAddress((void**)&pFh, g_Fh);
    cudaGetSymbolAddress((void**)&pMh, g_MEANh);
    cudaGetSymbolAddress((void**)&pF256h, g_F256h);
    cudaGetSymbolAddress((void**)&pCnt, g_cnt);
    cudaGetSymbolAddress((void**)&pOff, g_off);
    cudaGetSymbolAddress((void**)&pCur, g_cur);
    cudaGetSymbolAddress((void**)&pEl, g_elist);

    cudaFuncSetAttribute(flash_f16, cudaFuncAttributeMaxDynamicSharedMemorySize, FL_SMEM);
    cudaFuncSetAttribute(adj_sigmoid, cudaFuncAttributeMaxDynamicSharedMemorySize, ADJ_SMEM);
    cudaFuncSetAttribute(qkv_wmma, cudaFuncAttributeMaxDynamicSharedMemorySize, QKV_SMEM);
    cudaFuncSetAttribute(sage_wmma, cudaFuncAttributeMaxDynamicSharedMemorySize, QKV_SMEM);

    const float isc = 0.08838834764831845f;  // 1/sqrt(128)
    const int EW = (TN2 * DIM + 255) / 256;

    concat_x<<<EW, 256>>>(x1, x2, pX, pXh);
    // ---- build CSR once ----
    zero_i<<<(TN2 + 255) / 256, 256>>>(pCnt, TN2);
    zero_i<<<(TN2 + 255) / 256, 256>>>(pCur, TN2);
    edge_count<<<(NEDGE + 255) / 256, 256>>>(ei1, 0, pCnt);
    edge_count<<<(NEDGE + 255) / 256, 256>>>(ei2, NNODES, pCnt);
    scan_offsets<<<1, 1024>>>(pCnt, pOff);
    fill_edges<<<(NEDGE + 255) / 256, 256>>>(ei1, 0, pOff, pCur, pEl);
    fill_edges<<<(NEDGE + 255) / 256, 256>>>(ei2, NNODES, pOff, pCur, pEl);

    for (int L = 0; L < 2; L++) {
        qkv_wmma<<<TN2 / 128, 256, QKV_SMEM>>>(pXh, Wk[L], bk[L], 1.0f, 0, pKh, nullptr);
        qkv_wmma<<<TN2 / 128, 256, QKV_SMEM>>>(pXh, Wq[L], bq[L], isc, 0, pQh, nullptr);
        qkv_wmma<<<TN2 / 128, 256, QKV_SMEM>>>(pXh, Wv[L], bv[L], 1.0f, 1, nullptr, pV);
        vt_round_f16<<<TN2 / 64, 256>>>(pV, pVth);
        zero_f<<<(TN2 + 255) / 256, 256>>>(pL, TN2);
        dim3 gfl(TN2 / 128, 2);
        flash_f16<<<gfl, 256, FL_SMEM>>>(pQh, pKh, pVth, pOP, pL);
        build_feats2<<<EW, 256>>>(pX, pOP, pL, pF, pF256h);
        gather_mean<<<TN2, FDIM>>>(pF, pOff, pCnt, pEl, pMh);
        sage_wmma<<<TN2 / 128, 256, QKV_SMEM>>>(pMh, pF256h, Wl[L], Wr[L], bl[L],
                                                (L == 0) ? 1 : 0, pX, pXh);
    }

    round_f16<<<EW, 256>>>(pX, pFh);
    dim3 gf(TN2 / 128, TN2 / 128);
    adj_sigmoid<<<gf, 256, ADJ_SMEM>>>(pFh, out);
}

// round 17
// speedup vs baseline: 1.2606x; 1.2606x over previous
#include <cuda_runtime.h>
#include <cuda_fp16.h>
#include <mma.h>
#include <cstdint>
#include <math.h>

using namespace nvcuda;

#define NNODES 4096
#define TN2    8192
#define DIM    128
#define FDIM   256
#define NEDGE  65536

// ================= scratch (device globals; no allocation) =================
__device__ float g_X[TN2 * DIM];
__device__ float g_Vb[TN2 * DIM];
__device__ float g_F[TN2 * FDIM];
__device__ float g_L[TN2];            // exp row sums
__device__ float g_OP[2 * TN2 * DIM]; // PV partials (2 key-halves)
__device__ __half g_Xh[TN2 * DIM];    // fp16(X) for QKV linears
__device__ __half g_Qh[TN2 * DIM];    // fp16(Q * isc)
__device__ __half g_Kh[TN2 * DIM];    // fp16(K)
__device__ __half g_Vth[DIM * TN2];   // fp16(V^T)
__device__ __half g_Fh[TN2 * DIM];    // fp16(final feats) for adj
__device__ __half g_MEANh[TN2 * FDIM];
__device__ __half g_F256h[TN2 * FDIM];
// CSR for combined graph (both graphs, nodes 0..8191)
__device__ int g_cnt[TN2];
__device__ int g_off[TN2];
__device__ int g_cur[TN2];
__device__ int g_elist[2 * NEDGE];

// ================= small elementwise kernels =================
__global__ void concat_x(const float* __restrict__ x1, const float* __restrict__ x2,
                         float* __restrict__ X, __half* __restrict__ Xh) {
    int i = blockIdx.x * blockDim.x + threadIdx.x;
    if (i < TN2 * DIM) {
        float v = (i < NNODES * DIM) ? x1[i] : x2[i - NNODES * DIM];
        X[i] = v;
        Xh[i] = __float2half(v);
    }
}
__global__ void zero_f(float* __restrict__ p, int n) {
    int i = blockIdx.x * blockDim.x + threadIdx.x;
    if (i < n) p[i] = 0.f;
}
__global__ void zero_i(int* __restrict__ p, int n) {
    int i = blockIdx.x * blockDim.x + threadIdx.x;
    if (i < n) p[i] = 0;
}
// ---- CSR build (once; graph static across layers) ----
__global__ void edge_count(const int* __restrict__ ei, int off, int* __restrict__ cnt) {
    int e = blockIdx.x * blockDim.x + threadIdx.x;
    if (e < NEDGE) atomicAdd(&cnt[ei[NEDGE + e] + off], 1);
}
__global__ void scan_offsets(const int* __restrict__ cnt, int* __restrict__ off) {
    __shared__ int tsum[1024];
    int t = threadIdx.x;
    int local[8];
    int s = 0;
#pragma unroll
    for (int j = 0; j < 8; j++) { local[j] = s; s += cnt[t * 8 + j]; }
    tsum[t] = s;
    __syncthreads();
    for (int d = 1; d < 1024; d <<= 1) {
        int v = (t >= d) ? tsum[t - d] : 0;
        __syncthreads();
        tsum[t] += v;
        __syncthreads();
    }
    int base = (t == 0) ? 0 : tsum[t - 1];
#pragma unroll
    for (int j = 0; j < 8; j++) off[t * 8 + j] = base + local[j];
}
__global__ void fill_edges(const int* __restrict__ ei, int noff,
                           const int* __restrict__ off, int* __restrict__ cur,
                           int* __restrict__ elist) {
    int e = blockIdx.x * blockDim.x + threadIdx.x;
    if (e < NEDGE) {
        int src = ei[e] + noff;
        int dst = ei[NEDGE + e] + noff;
        int p = atomicAdd(&cur[dst], 1);
        elist[off[dst] + p] = src;
    }
}
// ---- gather-mean -> fp16 ----
__global__ void gather_mean(const float* __restrict__ F, const int* __restrict__ off,
                            const int* __restrict__ cnt, const int* __restrict__ elist,
                            __half* __restrict__ meanh) {
    int row = blockIdx.x;
    int c = threadIdx.x;
    int base = off[row], n = cnt[row];
    float s = 0.f;
    for (int i = 0; i < n; i++) {
        int src = elist[base + i];
        s += F[(size_t)src * FDIM + c];
    }
    meanh[(size_t)row * FDIM + c] = __float2half(s / (float)max(n, 1));
}
// F = [X, X - O], fp32 for gather + fp16 for sage lin_r
__global__ void build_feats2(const float* __restrict__ X, const float* __restrict__ OP,
                             const float* __restrict__ l, float* __restrict__ F,
                             __half* __restrict__ F256h) {
    int i = blockIdx.x * blockDim.x + threadIdx.x;
    if (i < TN2 * DIM) {
        int row = i >> 7, c = i & 127;
        float x = X[i];
        float o = (OP[i] + OP[TN2 * DIM + i]) / l[row];
        float d = x - o;
        F[row * FDIM + c] = x;
        F[row * FDIM + DIM + c] = d;
        F256h[(size_t)row * FDIM + c] = __float2half(x);
        F256h[(size_t)row * FDIM + DIM + c] = __float2half(d);
    }
}
__global__ void round_f16(const float* __restrict__ in, __half* __restrict__ out) {
    int i = blockIdx.x * blockDim.x + threadIdx.x;
    if (i < TN2 * DIM) out[i] = __float2half(in[i]);
}
// V [8192,128] fp32 -> Vt [128,8192] fp16 (64-key tiles)
__global__ void vt_round_f16(const float* __restrict__ V, __half* __restrict__ Vth) {
    __shared__ float t[64][132];
    int tid = threadIdx.x;
    int k0 = blockIdx.x * 64;
#pragma unroll
    for (int rep = 0; rep < 8; rep++) {
        int idx = rep * 256 + tid;
        int r = idx >> 5, c4 = (idx & 31) * 4;
        float4 v = *(const float4*)&V[(k0 + r) * DIM + c4];
        t[r][c4] = v.x; t[r][c4 + 1] = v.y; t[r][c4 + 2] = v.z; t[r][c4 + 3] = v.w;
    }
    __syncthreads();
    int d = tid >> 1, half_ = tid & 1;
    size_t base = (size_t)d * TN2 + k0 + half_ * 32;
#pragma unroll
    for (int j = 0; j < 32; j++)
        Vth[base + j] = __float2half(t[half_ * 32 + j][d]);
}

// ======== WMMA linear: C[128,128]/block = Ah[128,128] @ fp16(W*scale) + bias*scale ====
#define LSTR 136
#define LTILE (128 * LSTR)
#define QKV_SMEM (2 * LTILE * 2 + 16 * 132 * 4)  // 78080 B

__global__ __launch_bounds__(256) void qkv_wmma(
    const __half* __restrict__ Ah, const float* __restrict__ W,
    const float* __restrict__ bias, float scale, int mode,
    __half* __restrict__ outH, float* __restrict__ outF) {
    extern __shared__ char sm[];
    __half* sA = (__half*)sm;
    __half* sB = sA + LTILE;
    float* sBias = (float*)(sm + 2 * LTILE * 2);
    int tid = threadIdx.x, lane = tid & 31, w = tid >> 5;
    int m0 = blockIdx.x * 128;

#pragma unroll
    for (int rep = 0; rep < 8; rep++) {
        int u = rep * 256 + tid;
        int row = u >> 4, c8 = (u & 15) * 8;
        *(uint4*)&sA[row * LSTR + c8] = *(const uint4*)&Ah[(size_t)(m0 + row) * DIM + c8];
    }
#pragma unroll
    for (int rep = 0; rep < 16; rep++) {
        int u = rep * 256 + tid;
        int row = u >> 5, c4 = (u & 31) * 4;
        float4 v = *(const float4*)&W[row * DIM + c4];
        sB[row * LSTR + c4 + 0] = __float2half(v.x * scale);
        sB[row * LSTR + c4 + 1] = __float2half(v.y * scale);
        sB[row * LSTR + c4 + 2] = __float2half(v.z * scale);
        sB[row * LSTR + c4 + 3] = __float2half(v.w * scale);
    }
#pragma unroll
    for (int rep = 0; rep < 8; rep++) {
        int u = rep * 256 + tid;
        int row = u >> 7, c = u & 127;
        sBias[row * 132 + c] = bias[c] * scale;
    }
    __syncthreads();

    wmma::fragment<wmma::accumulator, 16, 16, 16, float> acc[8];
#pragma unroll
    for (int n = 0; n < 8; n++)
        wmma::load_matrix_sync(acc[n], sBias + n * 16, 132, wmma::mem_row_major);
#pragma unroll
    for (int ks = 0; ks < 8; ks++) {
        wmma::fragment<wmma::matrix_a, 16, 16, 16, __half, wmma::row_major> a;
        wmma::load_matrix_sync(a, sA + (w * 16) * LSTR + ks * 16, LSTR);
#pragma unroll
        for (int n = 0; n < 8; n++) {
            wmma::fragment<wmma::matrix_b, 16, 16, 16, __half, wmma::row_major> b;
            wmma::load_matrix_sync(b, sB + (ks * 16) * LSTR + n * 16, LSTR);
            wmma::mma_sync(acc[n], a, b, acc[n]);
        }
    }
    __syncthreads();

    float* mC = (float*)sm + w * (16 * 132);
#pragma unroll
    for (int n = 0; n < 8; n++)
        wmma::store_matrix_sync(mC + n * 16, acc[n], 132, wmma::mem_row_major);
    __syncwarp();
    int r = lane >> 1, c0 = (lane & 1) * 64;
    size_t gbase = (size_t)(m0 + w * 16 + r) * DIM + c0;
    if (mode == 0) {
#pragma unroll
        for (int j = 0; j < 64; j++) outH[gbase + j] = __float2half(mC[r * 132 + c0 + j]);
    } else {
#pragma unroll
        for (int j = 0; j < 64; j++) outF[gbase + j] = mC[r * 132 + c0 + j];
    }
}

// ======== WMMA fused SAGE: X = MEANh@Wl + bl + F256h@Wr (+relu); writes fp32+fp16 ====
__global__ __launch_bounds__(256) void sage_wmma(
    const __half* __restrict__ Mh, const __half* __restrict__ Fh256,
    const float* __restrict__ Wl, const float* __restrict__ Wr,
    const float* __restrict__ bl, int relu,
    float* __restrict__ Xout, __half* __restrict__ XhOut) {
    extern __shared__ char sm[];
    __half* sA = (__half*)sm;
    __half* sB = sA + LTILE;
    float* sBias = (float*)(sm + 2 * LTILE * 2);
    int tid = threadIdx.x, lane = tid & 31, w = tid >> 5;
    int m0 = blockIdx.x * 128;

#pragma unroll
    for (int rep = 0; rep < 8; rep++) {
        int u = rep * 256 + tid;
        int row = u >> 7, c = u & 127;
        sBias[row * 132 + c] = bl[c];
    }
    __syncthreads();
    wmma::fragment<wmma::accumulator, 16, 16, 16, float> acc[8];
#pragma unroll
    for (int n = 0; n < 8; n++)
        wmma::load_matrix_sync(acc[n], sBias + n * 16, 132, wmma::mem_row_major);

#pragma unroll
    for (int p = 0; p < 2; p++) {
        const __half* Ap = p ? Fh256 : Mh;
        const float* Wp = p ? Wr : Wl;
#pragma unroll
        for (int kc = 0; kc < 2; kc++) {
            __syncthreads();
#pragma unroll
            for (int rep = 0; rep < 8; rep++) {
                int u = rep * 256 + tid;
                int row = u >> 4, c8 = (u & 15) * 8;
                *(uint4*)&sA[row * LSTR + c8] =
                    *(const uint4*)&Ap[(size_t)(m0 + row) * FDIM + kc * 128 + c8];
            }
#pragma unroll
            for (int rep = 0; rep < 16; rep++) {
                int u = rep * 256 + tid;
                int row = u >> 5, c4 = (u & 31) * 4;
                float4 v = *(const float4*)&Wp[(kc * 128 + row) * DIM + c4];
                sB[row * LSTR + c4 + 0] = __float2half(v.x);
                sB[row * LSTR + c4 + 1] = __float2half(v.y);
                sB[row * LSTR + c4 + 2] = __float2half(v.z);
                sB[row * LSTR + c4 + 3] = __float2half(v.w);
            }
            __syncthreads();
#pragma unroll
            for (int ks = 0; ks < 8; ks++) {
                wmma::fragment<wmma::matrix_a, 16, 16, 16, __half, wmma::row_major> a;
                wmma::load_matrix_sync(a, sA + (w * 16) * LSTR + ks * 16, LSTR);
#pragma unroll
                for (int n = 0; n < 8; n++) {
                    wmma::fragment<wmma::matrix_b, 16, 16, 16, __half, wmma::row_major> b;
                    wmma::load_matrix_sync(b, sB + (ks * 16) * LSTR + n * 16, LSTR);
                    wmma::mma_sync(acc[n], a, b, acc[n]);
                }
            }
        }
    }
    __syncthreads();

    float* mC = (float*)sm + w * (16 * 132);
#pragma unroll
    for (int n = 0; n < 8; n++)
        wmma::store_matrix_sync(mC + n * 16, acc[n], 132, wmma::mem_row_major);
    __syncwarp();
    int r = lane >> 1, c0 = (lane & 1) * 64;
    size_t gbase = (size_t)(m0 + w * 16 + r) * DIM + c0;
#pragma unroll
    for (int j = 0; j < 64; j++) {
        float v = mC[r * 132 + c0 + j];
        if (relu) v = fmaxf(v, 0.f);
        Xout[gbase + j] = v;
        XhOut[gbase + j] = __float2half(v);
    }
}

// ======== flash attention: fp16, double-buffered K/V via register prefetch ========
// grid (64 q-blocks, 2 key-halves), 256 threads = 8 warps, warp owns 16 query rows.
// smem: Q | KVbuf0 | KVbuf1 | S(fp32, P fp16 overlaid after in-register exp pass)
#define QSTR 136
#define VSTR 72
#define OFF_Q   0
#define KVBUF   (64 * QSTR + 128 * VSTR)     // 17920 halves per buffer
#define OFF_KV0 (128 * QSTR)                 // 17408
#define OFF_KV1 (OFF_KV0 + KVBUF)
#define HB      ((OFF_KV1 + KVBUF) * 2)      // 106496 B
#define SB      (8 * 16 * 68 * 4)            // 34816 B
#define FL_SMEM (HB + SB)                    // 141312 B

__global__ __launch_bounds__(256, 1) void flash_f16(
    const __half* __restrict__ Qh, const __half* __restrict__ Kh,
    const __half* __restrict__ Vth, float* __restrict__ OP,
    float* __restrict__ lsum) {
    extern __shared__ char smc[];
    __half* sb = (__half*)smc;
    float* sS = (float*)(smc + HB);

    int tid = threadIdx.x, lane = tid & 31, w = tid >> 5;
    int m0 = blockIdx.x * 128;
    int kh = blockIdx.y;
    int kbase = kh * (TN2 / 2);

    // stage Q [128 x 128]
#pragma unroll
    for (int rep = 0; rep < 8; rep++) {
        int u = rep * 256 + tid;
        int row = u >> 4, c8 = (u & 15) * 8;
        *(uint4*)&sb[OFF_Q + row * QSTR + c8] =
            *(const uint4*)&Qh[(size_t)(m0 + row) * DIM + c8];
    }

    // per-thread staging coordinates (constant across chunks)
    int krow[4], kc8[4], vrow[4], vc8[4];
#pragma unroll
    for (int rep = 0; rep < 4; rep++) {
        int u = rep * 256 + tid;
        krow[rep] = u >> 4; kc8[rep] = (u & 15) * 8;
        vrow[rep] = u >> 3; vc8[rep] = (u & 7) * 8;
    }

    uint4 pre[8];
    auto loadKV = [&](int c) {
        int kc = kbase + c * 64;
#pragma unroll
        for (int rep = 0; rep < 4; rep++)
            pre[rep] = *(const uint4*)&Kh[(size_t)(kc + krow[rep]) * DIM + kc8[rep]];
#pragma unroll
        for (int rep = 0; rep < 4; rep++)
            pre[4 + rep] = *(const uint4*)&Vth[(size_t)vrow[rep] * TN2 + kc + vc8[rep]];
    };
    auto storeKV = [&](int buf) {
        __half* kb = sb + (buf ? OFF_KV1 : OFF_KV0);
        __half* vb = kb + 64 * QSTR;
#pragma unroll
        for (int rep = 0; rep < 4; rep++)
            *(uint4*)&kb[krow[rep] * QSTR + kc8[rep]] = pre[rep];
#pragma unroll
        for (int rep = 0; rep < 4; rep++)
            *(uint4*)&vb[vrow[rep] * VSTR + vc8[rep]] = pre[4 + rep];
    };

    wmma::fragment<wmma::accumulator, 16, 16, 16, float> oacc[8];
#pragma unroll
    for (int n = 0; n < 8; n++) wmma::fill_fragment(oacc[n], 0.f);
    float rs = 0.f;
    float* mS = sS + w * (16 * 68);
    __half* mP = (__half*)mS;          // P overlaid on S (stride 72)

    loadKV(0);
    storeKV(0);
    __syncthreads();

    for (int c = 0; c < 64; c++) {
        if (c < 63) loadKV(c + 1);     // prefetch in flight during compute
        __half* kb = sb + ((c & 1) ? OFF_KV1 : OFF_KV0);
        __half* vb = kb + 64 * QSTR;

        // S[16x64] = Q_w K^T
        wmma::fragment<wmma::accumulator, 16, 16, 16, float> sf[4];
#pragma unroll
        for (int n = 0; n < 4; n++) wmma::fill_fragment(sf[n], 0.f);
#pragma unroll
        for (int ks = 0; ks < 8; ks++) {
            wmma::fragment<wmma::matrix_a, 16, 16, 16, __half, wmma::row_major> a;
            wmma::load_matrix_sync(a, sb + OFF_Q + (w * 16) * QSTR + ks * 16, QSTR);
#pragma unroll
            for (int n = 0; n < 4; n++) {
                wmma::fragment<wmma::matrix_b, 16, 16, 16, __half, wmma::col_major> b;
                wmma::load_matrix_sync(b, kb + (n * 16) * QSTR + ks * 16, QSTR);
                wmma::mma_sync(sf[n], a, b, sf[n]);
            }
        }
#pragma unroll
        for (int n = 0; n < 4; n++)
            wmma::store_matrix_sync(mS + n * 16, sf[n], 68, wmma::mem_row_major);
        __syncwarp();

        // exp: read S into regs, then overwrite region with fp16 P
        {
            int r = lane >> 1, c0 = (lane & 1) * 32;
            float ev[32];
            float rsl = 0.f;
#pragma unroll
            for (int j = 0; j < 32; j++) {
                ev[j] = __expf(mS[r * 68 + c0 + j]);
                rsl += ev[j];
            }
            rs += rsl;
            __syncwarp();
#pragma unroll
            for (int j = 0; j < 32; j++)
                mP[r * 72 + c0 + j] = __float2half(ev[j]);
        }
        __syncwarp();

        // O += P V
#pragma unroll
        for (int kt = 0; kt < 4; kt++) {
            wmma::fragment<wmma::matrix_a, 16, 16, 16, __half, wmma::row_major> pa;
            wmma::load_matrix_sync(pa, mP + kt * 16, 72);
#pragma unroll
            for (int n = 0; n < 8; n++) {
                wmma::fragment<wmma::matrix_b, 16, 16, 16, __half, wmma::col_major> v;
                wmma::load_matrix_sync(v, vb + (n * 16) * VSTR + kt * 16, VSTR);
                wmma::mma_sync(oacc[n], pa, v, oacc[n]);
            }
        }

        if (c < 63) storeKV((c + 1) & 1);  // target buffer's readers passed prior barrier
        __syncthreads();
    }

    float* dst = OP + (size_t)kh * TN2 * DIM + (size_t)(m0 + w * 16) * DIM;
#pragma unroll
    for (int n = 0; n < 8; n++)
        wmma::store_matrix_sync(dst + n * 16, oacc[n], DIM, wmma::mem_row_major);
    rs += __shfl_xor_sync(0xffffffffu, rs, 1);
    if ((lane & 1) == 0) atomicAdd(&lsum[m0 + w * 16 + (lane >> 1)], rs);
}

// ======== fp16 NT GEMM + sigmoid: out = sigmoid(F F^T), K=128 staged whole ====
#define ASTR 136
#define ADJ_TILE (128 * ASTR)
#define ADJ_SMEM (2 * ADJ_TILE * 2)   // 69632 B -> 3 CTAs/SM

__global__ __launch_bounds__(256, 3) void adj_sigmoid(
    const __half* __restrict__ Fh, float* __restrict__ outF) {
    extern __shared__ __half smb[];
    int tid = threadIdx.x, w = tid >> 5;
    int wm = (w & 3) * 32, wn = (w >> 2) * 64;
    int m0 = blockIdx.x * 128, n0 = blockIdx.y * 128;
    __half* sA = smb;
    __half* sB = smb + ADJ_TILE;

#pragma unroll
    for (int rep = 0; rep < 8; rep++) {
        int u = rep * 256 + tid;
        int row = u >> 4, c8 = (u & 15) * 8;
        *(uint4*)&sA[row * ASTR + c8] = *(const uint4*)&Fh[(size_t)(m0 + row) * DIM + c8];
        *(uint4*)&sB[row * ASTR + c8] = *(const uint4*)&Fh[(size_t)(n0 + row) * DIM + c8];
    }
    __syncthreads();

    wmma::fragment<wmma::accumulator, 16, 16, 16, float> acc[2][4];
#pragma unroll
    for (int mt = 0; mt < 2; mt++)
#pragma unroll
        for (int nt = 0; nt < 4; nt++) wmma::fill_fragment(acc[mt][nt], 0.f);

#pragma unroll
    for (int ks = 0; ks < 8; ks++) {
        wmma::fragment<wmma::matrix_a, 16, 16, 16, __half, wmma::row_major> a[2];
#pragma unroll
        for (int mt = 0; mt < 2; mt++)
            wmma::load_matrix_sync(a[mt], sA + (wm + mt * 16) * ASTR + ks * 16, ASTR);
#pragma unroll
        for (int nt = 0; nt < 4; nt++) {
            wmma::fragment<wmma::matrix_b, 16, 16, 16, __half, wmma::col_major> b;
            wmma::load_matrix_sync(b, sB + (wn + nt * 16) * ASTR + ks * 16, ASTR);
#pragma unroll
            for (int mt = 0; mt < 2; mt++)
                wmma::mma_sync(acc[mt][nt], a[mt], b, acc[mt][nt]);
        }
    }

#pragma unroll
    for (int mt = 0; mt < 2; mt++)
#pragma unroll
        for (int nt = 0; nt < 4; nt++) {
#pragma unroll
            for (int i = 0; i < acc[mt][nt].num_elements; i++)
                acc[mt][nt].x[i] = 1.f / (1.f + __expf(-acc[mt][nt].x[i]));
            float* dst = outF + (size_t)(m0 + wm + mt * 16) * TN2 + n0 + wn + nt * 16;
            wmma::store_matrix_sync(dst, acc[mt][nt], TN2, wmma::mem_row_major);
        }
}

// ================= host orchestration =================
extern "C" void kernel_launch(void* const* d_in, const int* in_sizes, int n_in,
                              void* d_out, int out_size) {
    const float* x1 = (const float*)d_in[0];
    const float* x2 = (const float*)d_in[1];
    const int* ei1 = (const int*)d_in[2];
    const int* ei2 = (const int*)d_in[3];
    const float* Wk[2] = {(const float*)d_in[4], (const float*)d_in[13]};
    const float* bk[2] = {(const float*)d_in[5], (const float*)d_in[14]};
    const float* Wq[2] = {(const float*)d_in[6], (const float*)d_in[15]};
    const float* bq[2] = {(const float*)d_in[7], (const float*)d_in[16]};
    const float* Wv[2] = {(const float*)d_in[8], (const float*)d_in[17]};
    const float* bv[2] = {(const float*)d_in[9], (const float*)d_in[18]};
    const float* Wl[2] = {(const float*)d_in[10], (const float*)d_in[19]};
    const float* bl[2] = {(const float*)d_in[11], (const float*)d_in[20]};
    const float* Wr[2] = {(const float*)d_in[12], (const float*)d_in[21]};
    float* out = (float*)d_out;

    float *pX, *pV, *pF, *pL, *pOP;
    __half *pXh, *pQh, *pKh, *pVth, *pFh, *pMh, *pF256h;
    int *pCnt, *pOff, *pCur, *pEl;
    cudaGetSymbolAddress((void**)&pX, g_X);
    cudaGetSymbolAddress((void**)&pV, g_Vb);
    cudaGetSymbolAddress((void**)&pF, g_F);
    cudaGetSymbolAddress((void**)&pL, g_L);
    cudaGetSymbolAddress((void**)&pOP, g_OP);
    cudaGetSymbolAddress((void**)&pXh, g_Xh);
    cudaGetSymbolAddress((void**)&pQh, g_Qh);
    cudaGetSymbolAddress((void**)&pKh, g_Kh);
    cudaGetSymbolAddress((void**)&pVth, g_Vth);
    cudaGetSymbolAddress((void**)&pFh, g_Fh);
    cudaGetSymbolAddress((void**)&pMh, g_MEANh);
    cudaGetSymbolAddress((void**)&pF256h, g_F256h);
    cudaGetSymbolAddress((void**)&pCnt, g_cnt);
    cudaGetSymbolAddress((void**)&pOff, g_off);
    cudaGetSymbolAddress((void**)&pCur, g_cur);
    cudaGetSymbolAddress((void**)&pEl, g_elist);

    cudaFuncSetAttribute(flash_f16, cudaFuncAttributeMaxDynamicSharedMemorySize, FL_SMEM);
    cudaFuncSetAttribute(adj_sigmoid, cudaFuncAttributeMaxDynamicSharedMemorySize, ADJ_SMEM);
    cudaFuncSetAttribute(qkv_wmma, cudaFuncAttributeMaxDynamicSharedMemorySize, QKV_SMEM);
    cudaFuncSetAttribute(sage_wmma, cudaFuncAttributeMaxDynamicSharedMemorySize, QKV_SMEM);

    const float isc = 0.08838834764831845f;  // 1/sqrt(128)
    const int EW = (TN2 * DIM + 255) / 256;

    concat_x<<<EW, 256>>>(x1, x2, pX, pXh);
    // ---- build CSR once ----
    zero_i<<<(TN2 + 255) / 256, 256>>>(pCnt, TN2);
    zero_i<<<(TN2 + 255) / 256, 256>>>(pCur, TN2);
    edge_count<<<(NEDGE + 255) / 256, 256>>>(ei1, 0, pCnt);
    edge_count<<<(NEDGE + 255) / 256, 256>>>(ei2, NNODES, pCnt);
    scan_offsets<<<1, 1024>>>(pCnt, pOff);
    fill_edges<<<(NEDGE + 255) / 256, 256>>>(ei1, 0, pOff, pCur, pEl);
    fill_edges<<<(NEDGE + 255) / 256, 256>>>(ei2, NNODES, pOff, pCur, pEl);

    for (int L = 0; L < 2; L++) {
        qkv_wmma<<<TN2 / 128, 256, QKV_SMEM>>>(pXh, Wk[L], bk[L], 1.0f, 0, pKh, nullptr);
        qkv_wmma<<<TN2 / 128, 256, QKV_SMEM>>>(pXh, Wq[L], bq[L], isc, 0, pQh, nullptr);
        qkv_wmma<<<TN2 / 128, 256, QKV_SMEM>>>(pXh, Wv[L], bv[L], 1.0f, 1, nullptr, pV);
        vt_round_f16<<<TN2 / 64, 256>>>(pV, pVth);
        zero_f<<<(TN2 + 255) / 256, 256>>>(pL, TN2);
        dim3 gfl(TN2 / 128, 2);
        flash_f16<<<gfl, 256, FL_SMEM>>>(pQh, pKh, pVth, pOP, pL);
        build_feats2<<<EW, 256>>>(pX, pOP, pL, pF, pF256h);
        gather_mean<<<TN2, FDIM>>>(pF, pOff, pCnt, pEl, pMh);
        sage_wmma<<<TN2 / 128, 256, QKV_SMEM>>>(pMh, pF256h, Wl[L], Wr[L], bl[L],
                                                (L == 0) ? 1 : 0, pX, pXh);
    }

    round_f16<<<EW, 256>>>(pX, pFh);
    dim3 gf(TN2 / 128, TN2 / 128);
    adj_sigmoid<<<gf, 256, ADJ_SMEM>>>(pFh, out);
}